// round 6
// baseline (speedup 1.0000x reference)
#include <cuda_runtime.h>
#include <cuda_bf16.h>
#include <math.h>
#include <stdint.h>

#define BATCH 2
#define SEQ 2048
#define DMODEL 1024
#define NH 16
#define HD 64
#define DFF 4096
#define ROWS (BATCH*SEQ)   // 4096

// ================= scratch (__device__ globals; no runtime alloc) ==========
__device__ float g_x1[ROWS*DMODEL];
__device__ float g_src2[ROWS*DMODEL];
__device__ int   g_len[BATCH];
__device__ float g_bqkv[3072];
// activations as bf16 hi/lo
__device__ __nv_bfloat16 g_srch[ROWS*DMODEL];
__device__ __nv_bfloat16 g_srcl[ROWS*DMODEL];
__device__ __nv_bfloat16 g_attnh[ROWS*DMODEL];
__device__ __nv_bfloat16 g_attnl[ROWS*DMODEL];
__device__ __nv_bfloat16 g_s2h[ROWS*DMODEL];
__device__ __nv_bfloat16 g_s2l[ROWS*DMODEL];
__device__ __nv_bfloat16 g_ffh[(size_t)ROWS*DFF];
__device__ __nv_bfloat16 g_ffl[(size_t)ROWS*DFF];
// Q/K/V bf16 hi/lo, layout [B,H,S,hd]; Q pre-scaled by 0.125
__device__ __nv_bfloat16 g_qh[BATCH*NH*SEQ*HD];
__device__ __nv_bfloat16 g_ql[BATCH*NH*SEQ*HD];
__device__ __nv_bfloat16 g_kh[BATCH*NH*SEQ*HD];
__device__ __nv_bfloat16 g_kl[BATCH*NH*SEQ*HD];
__device__ __nv_bfloat16 g_vh[BATCH*NH*SEQ*HD];
__device__ __nv_bfloat16 g_vl[BATCH*NH*SEQ*HD];
// transposed + hi/lo split weights, bf16 [N,K]
__device__ __nv_bfloat16 g_wqkv_hi[3072*1024];
__device__ __nv_bfloat16 g_wqkv_lo[3072*1024];
__device__ __nv_bfloat16 g_wo_hi[1024*1024];
__device__ __nv_bfloat16 g_wo_lo[1024*1024];
__device__ __nv_bfloat16 g_w1_hi[4096*1024];
__device__ __nv_bfloat16 g_w1_lo[4096*1024];
__device__ __nv_bfloat16 g_w2_hi[1024*4096];
__device__ __nv_bfloat16 g_w2_lo[1024*4096];

// ================= helpers =================================================
__device__ __forceinline__ uint32_t smem_u32(const void* p) {
    uint32_t a;
    asm("{ .reg .u64 t; cvta.to.shared.u64 t, %1; cvt.u32.u64 %0, t; }" : "=r"(a) : "l"(p));
    return a;
}
__device__ __forceinline__ void ldsm4(uint32_t a, uint32_t& r0, uint32_t& r1,
                                      uint32_t& r2, uint32_t& r3) {
    asm volatile("ldmatrix.sync.aligned.m8n8.x4.shared.b16 {%0,%1,%2,%3}, [%4];"
        : "=r"(r0), "=r"(r1), "=r"(r2), "=r"(r3) : "r"(a));
}
__device__ __forceinline__ void ldsm4t(uint32_t a, uint32_t& r0, uint32_t& r1,
                                       uint32_t& r2, uint32_t& r3) {
    asm volatile("ldmatrix.sync.aligned.m8n8.x4.trans.shared.b16 {%0,%1,%2,%3}, [%4];"
        : "=r"(r0), "=r"(r1), "=r"(r2), "=r"(r3) : "r"(a));
}
__device__ __forceinline__ void mma_bf16(float* d, const uint32_t* a,
                                         uint32_t b0, uint32_t b1) {
    asm volatile("mma.sync.aligned.m16n8k16.row.col.f32.bf16.bf16.f32 "
        "{%0,%1,%2,%3}, {%4,%5,%6,%7}, {%8,%9}, {%0,%1,%2,%3};"
        : "+f"(d[0]), "+f"(d[1]), "+f"(d[2]), "+f"(d[3])
        : "r"(a[0]), "r"(a[1]), "r"(a[2]), "r"(a[3]), "r"(b0), "r"(b1));
}
__device__ __forceinline__ float gelu_exact(float x) {
    return 0.5f * x * (1.0f + erff(x * 0.70710678118654752f));
}
__device__ __forceinline__ uint32_t pack_bf2(float a, float b) {
    __nv_bfloat162 t = __floats2bfloat162_rn(a, b);
    return *(uint32_t*)&t;
}

// ================= len + bias concat (fused, launch #0) ====================
__global__ void len_k(const void* __restrict__ mask,
                      const float* __restrict__ bq, const float* __restrict__ bk,
                      const float* __restrict__ bv)
{
    if (blockIdx.x >= BATCH) {
        const int i = (blockIdx.x - BATCH) * 256 + threadIdx.x;
        if (i < 3072)
            g_bqkv[i] = (i < 1024) ? bq[i] : (i < 2048) ? bk[i-1024] : bv[i-2048];
        return;
    }
    const int b = blockIdx.x;
    __shared__ int sbyte, smin;
    if (threadIdx.x == 0) { sbyte = 0; smin = SEQ; }
    __syncthreads();
    const unsigned* w = (const unsigned*)mask;
    for (int i = threadIdx.x; i < 1024; i += blockDim.x)
        if (w[i] > 1u) { sbyte = 1; break; }
    __syncthreads();
    int local = SEQ;
    if (sbyte) {
        const unsigned char* m = (const unsigned char*)mask + (size_t)b * SEQ;
        for (int s = threadIdx.x; s < SEQ; s += blockDim.x)
            if (m[s]) { local = s; break; }
    } else {
        const int* m = (const int*)mask + (size_t)b * SEQ;
        for (int s = threadIdx.x; s < SEQ; s += blockDim.x)
            if (m[s]) { local = s; break; }
    }
    atomicMin(&smin, local);
    __syncthreads();
    if (threadIdx.x == 0) g_len[b] = smin;
}

// ================= fp32 -> bf16 hi/lo split (activations) ==================
__global__ void asplit_k(const float* __restrict__ x,
                         __nv_bfloat16* __restrict__ hi,
                         __nv_bfloat16* __restrict__ lo)
{
    const size_t i = ((size_t)blockIdx.x * 256 + threadIdx.x) * 4;
    const float4 v = *(const float4*)(x + i);
    uint2 h, l;
    h.x = pack_bf2(v.x, v.y);
    h.y = pack_bf2(v.z, v.w);
    const __nv_bfloat162 h0 = *(const __nv_bfloat162*)&h.x;
    const __nv_bfloat162 h1 = *(const __nv_bfloat162*)&h.y;
    l.x = pack_bf2(v.x - __bfloat162float(h0.x), v.y - __bfloat162float(h0.y));
    l.y = pack_bf2(v.z - __bfloat162float(h1.x), v.w - __bfloat162float(h1.y));
    *(uint2*)(hi + i) = h;
    *(uint2*)(lo + i) = l;
}

// ================= weight transpose + hi/lo split ==========================
__global__ void tsplit_k(const float* __restrict__ W,
                         __nv_bfloat16* __restrict__ hi,
                         __nv_bfloat16* __restrict__ lo, int K, int N)
{
    __shared__ float t[32][33];
    const int n0 = blockIdx.x * 32, k0 = blockIdx.y * 32;
    const int tx = threadIdx.x, ty = threadIdx.y;
    #pragma unroll
    for (int i = 0; i < 4; i++)
        t[ty + i*8][tx] = W[(size_t)(k0 + ty + i*8) * N + n0 + tx];
    __syncthreads();
    #pragma unroll
    for (int i = 0; i < 4; i++) {
        const float v = t[tx][ty + i*8];
        const __nv_bfloat16 h = __float2bfloat16(v);
        const __nv_bfloat16 l = __float2bfloat16(v - __bfloat162float(h));
        const size_t o = (size_t)(n0 + ty + i*8) * K + k0 + tx;
        hi[o] = h; lo[o] = l;
    }
}

// ================= HMMA bf16 split GEMM (cp.async 2-stage) =================
// C = A @ B^T; A = Ahi+Alo bf16 [M,K], B = Bhi+Blo bf16 [N,K]; 3-term split.
// Tile 128x128, K-chunk 32 double-buffered. 8 warps, warp tile 32(M) x 64(N).
// EPI 1: +bias(g_bqkv), scatter q/k/v hi/lo (q scaled 0.125)
// EPI 2: +bias +res(fp32), write C fp32
// EPI 3: +bias, exact GELU, write Ch/Cl bf16 hi/lo
#define CSTR 80                        // smem row stride bytes (32 bf16 + pad)
#define TSZ  10240                     // one 128-row tile (128*80)
#define STAGE (4*TSZ)                  // Ahi,Alo,Bhi,Blo
#define GEMM_SMEM (2*STAGE)            // 81920

template<int EPI>
__global__ __launch_bounds__(256, 2) void hgemm_k(
    const __nv_bfloat16* __restrict__ Ahi,
    const __nv_bfloat16* __restrict__ Alo,
    const __nv_bfloat16* __restrict__ Bhi,
    const __nv_bfloat16* __restrict__ Blo,
    const float* __restrict__ bias,
    const float* __restrict__ res,
    float* __restrict__ C,
    __nv_bfloat16* __restrict__ qh, __nv_bfloat16* __restrict__ ql,
    __nv_bfloat16* __restrict__ kh, __nv_bfloat16* __restrict__ kl,
    __nv_bfloat16* __restrict__ vh, __nv_bfloat16* __restrict__ vl,
    int N, int K)
{
    extern __shared__ char sm[];
    const uint32_t smb = smem_u32(sm);
    const int tid = threadIdx.x;
    const int wid = tid >> 5, lane = tid & 31;
    const int wm = wid & 3, wn = wid >> 2;
    const int row0 = blockIdx.y * 128;
    const int col0 = blockIdx.x * 128;

    // padded-row tile skip (row-local dead work; final LN zeroes those rows)
    if ((row0 & (SEQ-1)) >= g_len[row0 >> 11]) return;

    float acc[2][8][4];
    #pragma unroll
    for (int mb = 0; mb < 2; mb++)
        #pragma unroll
        for (int nb = 0; nb < 8; nb++)
            #pragma unroll
            for (int e = 0; e < 4; e++) acc[mb][nb][e] = 0.f;

    const int nch = K >> 5;
    const int lm_row  = lane & 15;
    const int lm_colb = (lane >> 4) * 16;

    // cp.async prefetch of one 32-col K-chunk into stage buffer
    auto prefetch = [&](int c, int buf) {
        const uint32_t sb = smb + (uint32_t)buf * STAGE;
        #pragma unroll
        for (int i = 0; i < 8; ++i) {
            const int f = i * 256 + tid;      // 0..2047
            const int arr = f >> 9;           // 0:Ahi 1:Alo 2:Bhi 3:Blo
            const int idx = f & 511;
            const int r = idx >> 2;
            const int sg = idx & 3;           // 16B segment
            const __nv_bfloat16* s = (arr == 0) ? Ahi : (arr == 1) ? Alo :
                                     (arr == 2) ? Bhi : Blo;
            const int grow = ((arr < 2) ? row0 : col0) + r;
            const __nv_bfloat16* gp = s + (size_t)grow * K + c * 32 + sg * 8;
            const uint32_t dst = sb + (uint32_t)(arr * TSZ + r * CSTR + sg * 16);
            asm volatile("cp.async.cg.shared.global [%0], [%1], 16;"
                         :: "r"(dst), "l"(gp));
        }
        asm volatile("cp.async.commit_group;" ::: "memory");
    };

    prefetch(0, 0);
    for (int c = 0; c < nch; ++c) {
        if (c + 1 < nch) {
            prefetch(c + 1, (c + 1) & 1);
            asm volatile("cp.async.wait_group 1;" ::: "memory");
        } else {
            asm volatile("cp.async.wait_group 0;" ::: "memory");
        }
        __syncthreads();

        const uint32_t bb = smb + (uint32_t)(c & 1) * STAGE;
        #pragma unroll
        for (int st = 0; st < 2; ++st) {
            const int kb = st * 32;           // byte offset of k16 slice
            uint32_t ah[2][4], al[2][4];
            #pragma unroll
            for (int mb = 0; mb < 2; ++mb) {
                const uint32_t arow = (uint32_t)((wm*32 + mb*16 + lm_row) * CSTR + lm_colb + kb);
                ldsm4(bb + arow,       ah[mb][0], ah[mb][1], ah[mb][2], ah[mb][3]);
                ldsm4(bb + TSZ + arow, al[mb][0], al[mb][1], al[mb][2], al[mb][3]);
            }
            #pragma unroll
            for (int np = 0; np < 4; ++np) {
                const uint32_t brow = (uint32_t)((wn*64 + np*16 + lm_row) * CSTR + lm_colb + kb);
                uint32_t bh0, bh1, bh2, bh3, bl0, bl1, bl2, bl3;
                ldsm4(bb + 2*TSZ + brow, bh0, bh1, bh2, bh3);
                ldsm4(bb + 3*TSZ + brow, bl0, bl1, bl2, bl3);
                #pragma unroll
                for (int mb = 0; mb < 2; ++mb) {
                    mma_bf16(acc[mb][np*2],   ah[mb], bh0, bh2);
                    mma_bf16(acc[mb][np*2],   ah[mb], bl0, bl2);
                    mma_bf16(acc[mb][np*2],   al[mb], bh0, bh2);
                    mma_bf16(acc[mb][np*2+1], ah[mb], bh1, bh3);
                    mma_bf16(acc[mb][np*2+1], ah[mb], bl1, bl3);
                    mma_bf16(acc[mb][np*2+1], al[mb], bh1, bh3);
                }
            }
        }
        __syncthreads();
    }

    // ---- epilogue ----
    const int g = lane >> 2;
    const int cpair = (lane & 3) * 2;
    #pragma unroll
    for (int mb = 0; mb < 2; ++mb) {
        #pragma unroll
        for (int half = 0; half < 2; ++half) {
            const int mrow = row0 + wm*32 + mb*16 + g + half*8;
            #pragma unroll
            for (int nb = 0; nb < 8; ++nb) {
                const int n = col0 + wn*64 + nb*8 + cpair;
                float2 o;
                o.x = acc[mb][nb][half*2]   + bias[n];
                o.y = acc[mb][nb][half*2+1] + bias[n+1];
                if (EPI == 1) {
                    const int buf = n >> 10;
                    if (buf == 0) { o.x *= 0.125f; o.y *= 0.125f; }
                    __nv_bfloat16* dh = (buf == 0) ? qh : (buf == 1) ? kh : vh;
                    __nv_bfloat16* dl = (buf == 0) ? ql : (buf == 1) ? kl : vl;
                    const int nn = n & 1023, h = nn >> 6, d = nn & 63;
                    const int b = mrow >> 11, s = mrow & 2047;
                    const size_t off = ((size_t)((b*NH + h)*SEQ + s))*HD + d;
                    const uint32_t hv = pack_bf2(o.x, o.y);
                    __nv_bfloat162 hv2 = *(__nv_bfloat162*)&hv;
                    const uint32_t lv = pack_bf2(o.x - __bfloat162float(hv2.x),
                                                 o.y - __bfloat162float(hv2.y));
                    *(uint32_t*)&dh[off] = hv;
                    *(uint32_t*)&dl[off] = lv;
                } else if (EPI == 2) {
                    const float2 r2 = *(const float2*)&res[(size_t)mrow * N + n];
                    o.x += r2.x; o.y += r2.y;
                    *(float2*)&C[(size_t)mrow * N + n] = o;
                } else {
                    o.x = gelu_exact(o.x); o.y = gelu_exact(o.y);
                    const size_t off = (size_t)mrow * N + n;
                    const uint32_t hv = pack_bf2(o.x, o.y);
                    __nv_bfloat162 hv2 = *(__nv_bfloat162*)&hv;
                    const uint32_t lv = pack_bf2(o.x - __bfloat162float(hv2.x),
                                                 o.y - __bfloat162float(hv2.y));
                    *(uint32_t*)&qh[off] = hv;   // qh/ql reused as Ch/Cl
                    *(uint32_t*)&ql[off] = lv;
                }
            }
        }
    }
}

// ================= flash attention, HMMA bf16 split ========================
// 128 q-rows per block, 8 warps, kv tiles of 64.
// smem: Khi @0, Klo @9216, Vhi @18432, Vlo @27648 (64 rows, stride 144B)
#define FLASH_SMEM 36864

__global__ __launch_bounds__(256) void flashb_k(
    const __nv_bfloat16* __restrict__ Qh, const __nv_bfloat16* __restrict__ Ql,
    const __nv_bfloat16* __restrict__ Kh, const __nv_bfloat16* __restrict__ Kl,
    const __nv_bfloat16* __restrict__ Vh, const __nv_bfloat16* __restrict__ Vl,
    __nv_bfloat16* __restrict__ Oh, __nv_bfloat16* __restrict__ Ol)
{
    extern __shared__ char sm[];
    const uint32_t smb = smem_u32(sm);
    const int qb = blockIdx.x, h = blockIdx.y, b = blockIdx.z;
    const int q0 = qb * 128;
    const int tid = threadIdx.x;
    const int wid = tid >> 5, lane = tid & 31;
    const int len = g_len[b];

    if (q0 >= len) return;   // downstream GEMM skips these row tiles

    const size_t base = ((size_t)(b*NH + h)) * SEQ * HD;
    const int qrow = q0 + wid*16 + (lane >> 2);

    uint32_t qhf[4][4], qlf[4][4];
    #pragma unroll
    for (int st = 0; st < 4; ++st)
        #pragma unroll
        for (int rg = 0; rg < 4; ++rg) {
            const int rr = qrow + (rg & 1) * 8;
            const int kk = st*16 + (rg >> 1)*8 + (lane & 3)*2;
            qhf[st][rg] = *(const uint32_t*)&Qh[base + (size_t)rr*HD + kk];
            qlf[st][rg] = *(const uint32_t*)&Ql[base + (size_t)rr*HD + kk];
        }

    float m[2] = {-1e30f, -1e30f}, l[2] = {0.f, 0.f};
    float o[8][4];
    #pragma unroll
    for (int nb = 0; nb < 8; nb++)
        #pragma unroll
        for (int e = 0; e < 4; e++) o[nb][e] = 0.f;

    const int kmax = min(q0 + 127, len - 1);
    for (int k0 = 0; k0 <= kmax; k0 += 64) {
        __syncthreads();
        for (int i = tid; i < 2048; i += 256) {
            const int arr = i >> 9;
            const int idx = i & 511;
            const int r = idx >> 3;
            const int cb = (idx & 7) * 16;
            const __nv_bfloat16* src = (arr == 0) ? Kh : (arr == 1) ? Kl :
                                       (arr == 2) ? Vh : Vl;
            const uint4 val = *(const uint4*)&src[base + (size_t)(k0 + r)*HD + (cb >> 1)];
            *(uint4*)(sm + arr*9216 + r*144 + cb) = val;
        }
        __syncthreads();

        float s[8][4];
        #pragma unroll
        for (int nb = 0; nb < 8; nb++)
            #pragma unroll
            for (int e = 0; e < 4; e++) s[nb][e] = 0.f;
        #pragma unroll
        for (int np = 0; np < 4; ++np) {
            #pragma unroll
            for (int st = 0; st < 4; ++st) {
                const uint32_t a = smb + (uint32_t)((np*16 + (lane & 15))*144 + ((lane >> 4)*16) + st*32);
                uint32_t kh0, kh1, kh2, kh3, kl0, kl1, kl2, kl3;
                ldsm4(a,        kh0, kh1, kh2, kh3);
                ldsm4(a + 9216, kl0, kl1, kl2, kl3);
                mma_bf16(s[np*2],   qhf[st], kh0, kh2);
                mma_bf16(s[np*2],   qhf[st], kl0, kl2);
                mma_bf16(s[np*2],   qlf[st], kh0, kh2);
                mma_bf16(s[np*2+1], qhf[st], kh1, kh3);
                mma_bf16(s[np*2+1], qhf[st], kl1, kl3);
                mma_bf16(s[np*2+1], qlf[st], kh1, kh3);
            }
        }

        if (k0 + 63 >= q0 || k0 + 63 >= len) {
            #pragma unroll
            for (int nb = 0; nb < 8; ++nb)
                #pragma unroll
                for (int e = 0; e < 4; ++e) {
                    const int qq = qrow + (e >> 1) * 8;
                    const int kk = k0 + nb*8 + (lane & 3)*2 + (e & 1);
                    if (kk > qq || kk >= len) s[nb][e] = -1e30f;
                }
        }

        #pragma unroll
        for (int hh = 0; hh < 2; ++hh) {
            float tm = -1e30f;
            #pragma unroll
            for (int nb = 0; nb < 8; ++nb)
                tm = fmaxf(tm, fmaxf(s[nb][hh*2], s[nb][hh*2+1]));
            tm = fmaxf(tm, __shfl_xor_sync(0xffffffffu, tm, 1));
            tm = fmaxf(tm, __shfl_xor_sync(0xffffffffu, tm, 2));
            const float mn = fmaxf(m[hh], tm);
            const float alpha = __expf(m[hh] - mn);
            m[hh] = mn;
            float rs = 0.f;
            #pragma unroll
            for (int nb = 0; nb < 8; ++nb) {
                s[nb][hh*2]   = __expf(s[nb][hh*2]   - mn);
                s[nb][hh*2+1] = __expf(s[nb][hh*2+1] - mn);
                rs += s[nb][hh*2] + s[nb][hh*2+1];
            }
            rs += __shfl_xor_sync(0xffffffffu, rs, 1);
            rs += __shfl_xor_sync(0xffffffffu, rs, 2);
            l[hh] = l[hh]*alpha + rs;
            #pragma unroll
            for (int nb = 0; nb < 8; ++nb) {
                o[nb][hh*2] *= alpha; o[nb][hh*2+1] *= alpha;
            }
        }

        #pragma unroll
        for (int st = 0; st < 4; ++st) {
            uint32_t ph[4], pl[4];
            #pragma unroll
            for (int j = 0; j < 2; ++j) {
                const float e0 = s[2*st+j][0], e1 = s[2*st+j][1];
                const float e2 = s[2*st+j][2], e3 = s[2*st+j][3];
                const uint32_t hv01 = pack_bf2(e0, e1);
                const uint32_t hv23 = pack_bf2(e2, e3);
                const __nv_bfloat162 h01 = *(const __nv_bfloat162*)&hv01;
                const __nv_bfloat162 h23 = *(const __nv_bfloat162*)&hv23;
                ph[(j ? 2 : 0)] = hv01;
                ph[(j ? 3 : 1)] = hv23;
                pl[(j ? 2 : 0)] = pack_bf2(e0 - __bfloat162float(h01.x),
                                           e1 - __bfloat162float(h01.y));
                pl[(j ? 3 : 1)] = pack_bf2(e2 - __bfloat162float(h23.x),
                                           e3 - __bfloat162float(h23.y));
            }
            #pragma unroll
            for (int np = 0; np < 4; ++np) {
                const uint32_t a = smb + 18432u +
                    (uint32_t)((st*16 + (lane & 15))*144 + (np*16 + (lane >> 4)*8)*2);
                uint32_t vh0, vh1, vh2, vh3, vl0, vl1, vl2, vl3;
                ldsm4t(a,        vh0, vh1, vh2, vh3);
                ldsm4t(a + 9216, vl0, vl1, vl2, vl3);
                mma_bf16(o[np*2],   ph, vh0, vh1);
                mma_bf16(o[np*2],   pl, vh0, vh1);
                mma_bf16(o[np*2],   ph, vl0, vl1);
                mma_bf16(o[np*2+1], ph, vh2, vh3);
                mma_bf16(o[np*2+1], pl, vh2, vh3);
                mma_bf16(o[np*2+1], ph, vl2, vl3);
            }
        }
    }

    #pragma unroll
    for (int hh = 0; hh < 2; ++hh) {
        const float inv = 1.f / l[hh];
        const int qq = qrow + hh*8;
        #pragma unroll
        for (int nb = 0; nb < 8; ++nb) {
            const float ox = o[nb][hh*2]   * inv;
            const float oy = o[nb][hh*2+1] * inv;
            const size_t off = ((size_t)(b*SEQ + qq))*DMODEL + h*HD + nb*8 + (lane & 3)*2;
            const uint32_t hv = pack_bf2(ox, oy);
            __nv_bfloat162 hv2 = *(__nv_bfloat162*)&hv;
            const uint32_t lv = pack_bf2(ox - __bfloat162float(hv2.x),
                                         oy - __bfloat162float(hv2.y));
            *(uint32_t*)&Oh[off] = hv;
            *(uint32_t*)&Ol[off] = lv;
        }
    }
}

// ================= LayerNorm ===============================================
// FIN=0: write y fp32 + yh/yl bf16 hi/lo, skip padded rows.
// FIN=1: write y fp32, zero padded rows.
template<int FIN>
__global__ __launch_bounds__(256, 1) void layernorm_k(
    const float* __restrict__ x, const float* __restrict__ g,
    const float* __restrict__ be, float* __restrict__ y,
    __nv_bfloat16* __restrict__ yh, __nv_bfloat16* __restrict__ yl)
{
    const int row = blockIdx.x;
    const int tid = threadIdx.x;
    const int b = row >> 11, sidx = row & 2047;
    const bool padded = sidx >= g_len[b];
    if (padded) {
        if (FIN == 1)
            *(float4*)(y + (size_t)row*DMODEL + tid*4) = make_float4(0.f, 0.f, 0.f, 0.f);
        return;
    }
    const float4 v = *(const float4*)(x + (size_t)row*DMODEL + tid*4);
    float s  = v.x + v.y + v.z + v.w;
    float s2 = v.x*v.x + v.y*v.y + v.z*v.z + v.w*v.w;

    __shared__ float red[2][8];
    const int lane = tid & 31, warp = tid >> 5;
    #pragma unroll
    for (int off = 16; off > 0; off >>= 1) {
        s  += __shfl_xor_sync(0xffffffffu, s, off);
        s2 += __shfl_xor_sync(0xffffffffu, s2, off);
    }
    if (lane == 0) { red[0][warp] = s; red[1][warp] = s2; }
    __syncthreads();
    float ts = 0.f, ts2 = 0.f;
    #pragma unroll
    for (int w = 0; w < 8; w++) { ts += red[0][w]; ts2 += red[1][w]; }
    const float mu  = ts * (1.f/DMODEL);
    const float var = ts2 * (1.f/DMODEL) - mu*mu;
    const float r   = rsqrtf(var + 1e-5f);

    const float4 gg = *(const float4*)(g  + tid*4);
    const float4 bb = *(const float4*)(be + tid*4);
    float4 o;
    o.x = (v.x - mu)*r*gg.x + bb.x;
    o.y = (v.y - mu)*r*gg.y + bb.y;
    o.z = (v.z - mu)*r*gg.z + bb.z;
    o.w = (v.w - mu)*r*gg.w + bb.w;
    *(float4*)(y + (size_t)row*DMODEL + tid*4) = o;
    if (FIN == 0) {
        const size_t off = (size_t)row*DMODEL + tid*4;
        uint2 h, l;
        h.x = pack_bf2(o.x, o.y);
        h.y = pack_bf2(o.z, o.w);
        const __nv_bfloat162 h0 = *(const __nv_bfloat162*)&h.x;
        const __nv_bfloat162 h1 = *(const __nv_bfloat162*)&h.y;
        l.x = pack_bf2(o.x - __bfloat162float(h0.x), o.y - __bfloat162float(h0.y));
        l.y = pack_bf2(o.z - __bfloat162float(h1.x), o.w - __bfloat162float(h1.y));
        *(uint2*)(yh + off) = h;
        *(uint2*)(yl + off) = l;
    }
}

// ================= launch ==================================================
extern "C" void kernel_launch(void* const* d_in, const int* in_sizes, int n_in,
                              void* d_out, int out_size)
{
    (void)in_sizes; (void)n_in; (void)out_size;
    const float* src = (const float*)d_in[0];
    const void* pad = d_in[2];
    const float *Wq = (const float*)d_in[3],  *bq = (const float*)d_in[4];
    const float *Wk = (const float*)d_in[5],  *bk = (const float*)d_in[6];
    const float *Wv = (const float*)d_in[7],  *bv = (const float*)d_in[8];
    const float *Wo = (const float*)d_in[9],  *bo = (const float*)d_in[10];
    const float *W1 = (const float*)d_in[11], *b1 = (const float*)d_in[12];
    const float *W2 = (const float*)d_in[13], *b2 = (const float*)d_in[14];
    const float *g1 = (const float*)d_in[15], *be1 = (const float*)d_in[16];
    const float *g2 = (const float*)d_in[17], *be2 = (const float*)d_in[18];
    float* out = (float*)d_out;

    float *x1, *src2, *bqkv;
    __nv_bfloat16 *srch, *srcl, *attnh, *attnl, *s2h, *s2l, *ffh, *ffl;
    __nv_bfloat16 *qh, *ql, *kh, *kl, *vh, *vl;
    __nv_bfloat16 *wqh, *wql, *woh, *wol, *w1h, *w1l, *w2h, *w2l;
    cudaGetSymbolAddress((void**)&x1,    g_x1);
    cudaGetSymbolAddress((void**)&src2,  g_src2);
    cudaGetSymbolAddress((void**)&bqkv,  g_bqkv);
    cudaGetSymbolAddress((void**)&srch,  g_srch);
    cudaGetSymbolAddress((void**)&srcl,  g_srcl);
    cudaGetSymbolAddress((void**)&attnh, g_attnh);
    cudaGetSymbolAddress((void**)&attnl, g_attnl);
    cudaGetSymbolAddress((void**)&s2h,   g_s2h);
    cudaGetSymbolAddress((void**)&s2l,   g_s2l);
    cudaGetSymbolAddress((void**)&ffh,   g_ffh);
    cudaGetSymbolAddress((void**)&ffl,   g_ffl);
    cudaGetSymbolAddress((void**)&qh,    g_qh);
    cudaGetSymbolAddress((void**)&ql,    g_ql);
    cudaGetSymbolAddress((void**)&kh,    g_kh);
    cudaGetSymbolAddress((void**)&kl,    g_kl);
    cudaGetSymbolAddress((void**)&vh,    g_vh);
    cudaGetSymbolAddress((void**)&vl,    g_vl);
    cudaGetSymbolAddress((void**)&wqh,   g_wqkv_hi);
    cudaGetSymbolAddress((void**)&wql,   g_wqkv_lo);
    cudaGetSymbolAddress((void**)&woh,   g_wo_hi);
    cudaGetSymbolAddress((void**)&wol,   g_wo_lo);
    cudaGetSymbolAddress((void**)&w1h,   g_w1_hi);
    cudaGetSymbolAddress((void**)&w1l,   g_w1_lo);
    cudaGetSymbolAddress((void**)&w2h,   g_w2_hi);
    cudaGetSymbolAddress((void**)&w2l,   g_w2_lo);

    cudaFuncSetAttribute(hgemm_k<1>, cudaFuncAttributeMaxDynamicSharedMemorySize, GEMM_SMEM);
    cudaFuncSetAttribute(hgemm_k<2>, cudaFuncAttributeMaxDynamicSharedMemorySize, GEMM_SMEM);
    cudaFuncSetAttribute(hgemm_k<3>, cudaFuncAttributeMaxDynamicSharedMemorySize, GEMM_SMEM);
    cudaFuncSetAttribute(flashb_k, cudaFuncAttributeMaxDynamicSharedMemorySize, FLASH_SMEM);

    const dim3 tb(32, 8);
    // launch order arranged so ncu (-s 5 -c 1) profiles hgemm_k<1>
    len_k<<<14, 256>>>(pad, bq, bk, bv);                               // 0
    asplit_k<<<ROWS*DMODEL/1024, 256>>>(src, srch, srcl);              // 1
    tsplit_k<<<dim3(32, 32), tb>>>(Wq, wqh,             wql,             1024, 1024); // 2
    tsplit_k<<<dim3(32, 32), tb>>>(Wk, wqh + 1024*1024, wql + 1024*1024, 1024, 1024); // 3
    tsplit_k<<<dim3(32, 32), tb>>>(Wv, wqh + 2048*1024, wql + 2048*1024, 1024, 1024); // 4
    // 5: QKV fused GEMM [4096,1024]@[1024,3072] -> bf16 hi/lo q,k,v
    hgemm_k<1><<<dim3(24, 32), 256, GEMM_SMEM>>>(srch, srcl, wqh, wql, bqkv, nullptr,
                                                 nullptr, qh, ql, kh, kl, vh, vl,
                                                 3072, 1024);
    tsplit_k<<<dim3(32, 32), tb>>>(Wo, woh, wol, 1024, 1024);          // 6
    tsplit_k<<<dim3(128, 32), tb>>>(W1, w1h, w1l, 1024, 4096);         // 7
    tsplit_k<<<dim3(32, 128), tb>>>(W2, w2h, w2l, 4096, 1024);         // 8
    flashb_k<<<dim3(SEQ/128, NH, BATCH), 256, FLASH_SMEM>>>(qh, ql, kh, kl, vh, vl,
                                                            attnh, attnl);   // 9
    hgemm_k<2><<<dim3(8, 32), 256, GEMM_SMEM>>>(attnh, attnl, woh, wol, bo, src, x1,
                                                nullptr, nullptr, nullptr, nullptr,
                                                nullptr, nullptr, 1024, 1024);
    layernorm_k<0><<<ROWS, 256>>>(x1, g1, be1, src2, s2h, s2l);
    hgemm_k<3><<<dim3(32, 32), 256, GEMM_SMEM>>>(s2h, s2l, w1h, w1l, b1, nullptr,
                                                 nullptr, ffh, ffl, nullptr, nullptr,
                                                 nullptr, nullptr, 4096, 1024);
    hgemm_k<2><<<dim3(8, 32), 256, GEMM_SMEM>>>(ffh, ffl, w2h, w2l, b2, src2, x1,
                                                nullptr, nullptr, nullptr, nullptr,
                                                nullptr, nullptr, 1024, 4096);
    layernorm_k<1><<<ROWS, 256>>>(x1, g2, be2, out, nullptr, nullptr);
}

// round 7
// speedup vs baseline: 1.0585x; 1.0585x over previous
#include <cuda_runtime.h>
#include <cuda_bf16.h>
#include <math.h>
#include <stdint.h>

#define BATCH 2
#define SEQ 2048
#define DMODEL 1024
#define NH 16
#define HD 64
#define DFF 4096
#define ROWS (BATCH*SEQ)   // 4096

// ================= scratch (__device__ globals; no runtime alloc) ==========
__device__ float g_attn[ROWS*DMODEL];
__device__ float g_x1[ROWS*DMODEL];
__device__ float g_src2[ROWS*DMODEL];
__device__ float g_ff[(size_t)ROWS*DFF];
__device__ int   g_len[BATCH];
// Q/K/V as bf16 hi/lo pairs, layout [B,H,S,hd]; Q pre-scaled by 0.125
__device__ __nv_bfloat16 g_qh[BATCH*NH*SEQ*HD];
__device__ __nv_bfloat16 g_ql[BATCH*NH*SEQ*HD];
__device__ __nv_bfloat16 g_kh[BATCH*NH*SEQ*HD];
__device__ __nv_bfloat16 g_kl[BATCH*NH*SEQ*HD];
__device__ __nv_bfloat16 g_vh[BATCH*NH*SEQ*HD];
__device__ __nv_bfloat16 g_vl[BATCH*NH*SEQ*HD];
// transposed + hi/lo split weights, bf16 [N,K]
__device__ __nv_bfloat16 g_wqkv_hi[3072*1024];
__device__ __nv_bfloat16 g_wqkv_lo[3072*1024];
__device__ __nv_bfloat16 g_wo_hi[1024*1024];
__device__ __nv_bfloat16 g_wo_lo[1024*1024];
__device__ __nv_bfloat16 g_w1_hi[4096*1024];
__device__ __nv_bfloat16 g_w1_lo[4096*1024];
__device__ __nv_bfloat16 g_w2_hi[1024*4096];
__device__ __nv_bfloat16 g_w2_lo[1024*4096];
__device__ float g_bqkv[3072];

// ================= helpers =================================================
__device__ __forceinline__ uint32_t smem_u32(const void* p) {
    uint32_t a;
    asm("{ .reg .u64 t; cvta.to.shared.u64 t, %1; cvt.u32.u64 %0, t; }" : "=r"(a) : "l"(p));
    return a;
}
__device__ __forceinline__ void ldsm4(uint32_t a, uint32_t& r0, uint32_t& r1,
                                      uint32_t& r2, uint32_t& r3) {
    asm volatile("ldmatrix.sync.aligned.m8n8.x4.shared.b16 {%0,%1,%2,%3}, [%4];"
        : "=r"(r0), "=r"(r1), "=r"(r2), "=r"(r3) : "r"(a));
}
__device__ __forceinline__ void ldsm4t(uint32_t a, uint32_t& r0, uint32_t& r1,
                                       uint32_t& r2, uint32_t& r3) {
    asm volatile("ldmatrix.sync.aligned.m8n8.x4.trans.shared.b16 {%0,%1,%2,%3}, [%4];"
        : "=r"(r0), "=r"(r1), "=r"(r2), "=r"(r3) : "r"(a));
}
__device__ __forceinline__ void mma_bf16(float* d, const uint32_t* a,
                                         uint32_t b0, uint32_t b1) {
    asm volatile("mma.sync.aligned.m16n8k16.row.col.f32.bf16.bf16.f32 "
        "{%0,%1,%2,%3}, {%4,%5,%6,%7}, {%8,%9}, {%0,%1,%2,%3};"
        : "+f"(d[0]), "+f"(d[1]), "+f"(d[2]), "+f"(d[3])
        : "r"(a[0]), "r"(a[1]), "r"(a[2]), "r"(a[3]), "r"(b0), "r"(b1));
}
__device__ __forceinline__ float gelu_exact(float x) {
    return 0.5f * x * (1.0f + erff(x * 0.70710678118654752f));
}
__device__ __forceinline__ uint32_t pack_bf2(float a, float b) {
    __nv_bfloat162 t = __floats2bfloat162_rn(a, b);
    return *(uint32_t*)&t;
}

// ================= seq lengths (dtype-robust: int32 or uint8) ==============
__global__ void len_k(const void* __restrict__ mask)
{
    const int b = blockIdx.x;
    __shared__ int sbyte, smin;
    if (threadIdx.x == 0) { sbyte = 0; smin = SEQ; }
    __syncthreads();
    const unsigned* w = (const unsigned*)mask;
    for (int i = threadIdx.x; i < 1024; i += blockDim.x)
        if (w[i] > 1u) { sbyte = 1; break; }
    __syncthreads();
    int local = SEQ;
    if (sbyte) {
        const unsigned char* m = (const unsigned char*)mask + (size_t)b * SEQ;
        for (int s = threadIdx.x; s < SEQ; s += blockDim.x)
            if (m[s]) { local = s; break; }
    } else {
        const int* m = (const int*)mask + (size_t)b * SEQ;
        for (int s = threadIdx.x; s < SEQ; s += blockDim.x)
            if (m[s]) { local = s; break; }
    }
    atomicMin(&smin, local);
    __syncthreads();
    if (threadIdx.x == 0) g_len[b] = smin;
}

// ================= weight transpose + hi/lo split ==========================
__global__ void tsplit_k(const float* __restrict__ W,
                         __nv_bfloat16* __restrict__ hi,
                         __nv_bfloat16* __restrict__ lo, int K, int N)
{
    __shared__ float t[32][33];
    const int n0 = blockIdx.x * 32, k0 = blockIdx.y * 32;
    const int tx = threadIdx.x, ty = threadIdx.y;
    #pragma unroll
    for (int i = 0; i < 4; i++)
        t[ty + i*8][tx] = W[(size_t)(k0 + ty + i*8) * N + n0 + tx];
    __syncthreads();
    #pragma unroll
    for (int i = 0; i < 4; i++) {
        const float v = t[tx][ty + i*8];
        const __nv_bfloat16 h = __float2bfloat16(v);
        const __nv_bfloat16 l = __float2bfloat16(v - __bfloat162float(h));
        const size_t o = (size_t)(n0 + ty + i*8) * K + k0 + tx;
        hi[o] = h; lo[o] = l;
    }
}

__global__ void catb_k(const float* __restrict__ a, const float* __restrict__ b,
                       const float* __restrict__ c)
{
    const int i = blockIdx.x * 256 + threadIdx.x;
    if (i < 3072) g_bqkv[i] = (i < 1024) ? a[i] : (i < 2048) ? b[i-1024] : c[i-2048];
}

// ================= HMMA bf16 split GEMM ====================================
// Tile 128x128, K-chunk 64. 8 warps, warp tile 32(M) x 64(N).
// EPI 1: +bias, scatter q/k/v as bf16 hi/lo (q scaled 0.125)
// EPI 2: +bias +res; EPI 3: +bias, exact GELU.
#define ASTR 144
#define SM_AHI 0
#define SM_ALO (128*ASTR)
#define SM_BHI (2*128*ASTR)
#define SM_BLO (3*128*ASTR)
#define GEMM_SMEM (4*128*ASTR)        // 73728

template<int EPI>
__global__ __launch_bounds__(256, 2) void hgemm_k(
    const float* __restrict__ A,
    const __nv_bfloat16* __restrict__ Bhi,
    const __nv_bfloat16* __restrict__ Blo,
    const float* __restrict__ bias,
    const float* __restrict__ res,
    float* __restrict__ C,
    __nv_bfloat16* __restrict__ qh, __nv_bfloat16* __restrict__ ql,
    __nv_bfloat16* __restrict__ kh, __nv_bfloat16* __restrict__ kl,
    __nv_bfloat16* __restrict__ vh, __nv_bfloat16* __restrict__ vl,
    int N, int K)
{
    extern __shared__ char sm[];
    const uint32_t smb = smem_u32(sm);
    const int tid = threadIdx.x;
    const int wid = tid >> 5, lane = tid & 31;
    const int wm = wid & 3, wn = wid >> 2;
    const int row0 = blockIdx.y * 128;
    const int col0 = blockIdx.x * 128;

    // padded-row tile skip: rows >= len are row-local dead work
    // (final LN zeroes them; attention never reads K/V >= len)
    if ((row0 & (SEQ-1)) >= g_len[row0 >> 11]) return;

    float acc[2][8][4];
    #pragma unroll
    for (int mb = 0; mb < 2; mb++)
        #pragma unroll
        for (int nb = 0; nb < 8; nb++)
            #pragma unroll
            for (int e = 0; e < 4; e++) acc[mb][nb][e] = 0.f;

    const int nch = K >> 6;
    const int lm_row  = lane & 15;
    const int lm_colb = (lane >> 4) * 16;

    for (int c = 0; c < nch; ++c) {
        __syncthreads();
        const float* Ab = A + (size_t)row0 * K + c * 64;
        #pragma unroll
        for (int i = 0; i < 8; ++i) {
            const int f = i * 256 + tid;
            const int r = f >> 4;
            const int cc = (f & 15) * 4;
            const float4 v = *(const float4*)(Ab + (size_t)r * K + cc);
            const __nv_bfloat16 h0 = __float2bfloat16(v.x), h1 = __float2bfloat16(v.y);
            const __nv_bfloat16 h2 = __float2bfloat16(v.z), h3 = __float2bfloat16(v.w);
            const uint32_t off = (uint32_t)(r * ASTR + cc * 2);
            *(uint32_t*)(sm + SM_AHI + off)     = pack_bf2(__bfloat162float(h0), __bfloat162float(h1));
            *(uint32_t*)(sm + SM_AHI + off + 4) = pack_bf2(__bfloat162float(h2), __bfloat162float(h3));
            *(uint32_t*)(sm + SM_ALO + off)     = pack_bf2(v.x - __bfloat162float(h0), v.y - __bfloat162float(h1));
            *(uint32_t*)(sm + SM_ALO + off + 4) = pack_bf2(v.z - __bfloat162float(h2), v.w - __bfloat162float(h3));
        }
        #pragma unroll
        for (int i = 0; i < 8; ++i) {
            const int f = i * 256 + tid;
            const int arr = f >> 10;
            const int idx = f & 1023;
            const int r = idx >> 3;
            const int cb = (idx & 7) * 16;
            const __nv_bfloat16* srcb = arr ? Blo : Bhi;
            const uint4 v = *(const uint4*)(srcb + (size_t)(col0 + r) * K + c * 64 + (cb >> 1));
            *(uint4*)(sm + (arr ? SM_BLO : SM_BHI) + r * ASTR + cb) = v;
        }
        __syncthreads();

        #pragma unroll
        for (int st = 0; st < 4; ++st) {
            const int kb = st * 32;
            uint32_t ah[2][4], al[2][4];
            #pragma unroll
            for (int mb = 0; mb < 2; ++mb) {
                const uint32_t arow = (uint32_t)((wm*32 + mb*16 + lm_row) * ASTR + lm_colb + kb);
                ldsm4(smb + SM_AHI + arow, ah[mb][0], ah[mb][1], ah[mb][2], ah[mb][3]);
                ldsm4(smb + SM_ALO + arow, al[mb][0], al[mb][1], al[mb][2], al[mb][3]);
            }
            #pragma unroll
            for (int np = 0; np < 4; ++np) {
                const uint32_t brow = (uint32_t)((wn*64 + np*16 + lm_row) * ASTR + lm_colb + kb);
                uint32_t bh0, bh1, bh2, bh3, bl0, bl1, bl2, bl3;
                ldsm4(smb + SM_BHI + brow, bh0, bh1, bh2, bh3);
                ldsm4(smb + SM_BLO + brow, bl0, bl1, bl2, bl3);
                #pragma unroll
                for (int mb = 0; mb < 2; ++mb) {
                    mma_bf16(acc[mb][np*2],   ah[mb], bh0, bh2);
                    mma_bf16(acc[mb][np*2],   ah[mb], bl0, bl2);
                    mma_bf16(acc[mb][np*2],   al[mb], bh0, bh2);
                    mma_bf16(acc[mb][np*2+1], ah[mb], bh1, bh3);
                    mma_bf16(acc[mb][np*2+1], ah[mb], bl1, bl3);
                    mma_bf16(acc[mb][np*2+1], al[mb], bh1, bh3);
                }
            }
        }
    }

    const int g = lane >> 2;
    const int cpair = (lane & 3) * 2;
    #pragma unroll
    for (int mb = 0; mb < 2; ++mb) {
        #pragma unroll
        for (int half = 0; half < 2; ++half) {
            const int mrow = row0 + wm*32 + mb*16 + g + half*8;
            #pragma unroll
            for (int nb = 0; nb < 8; ++nb) {
                const int n = col0 + wn*64 + nb*8 + cpair;
                float2 o;
                o.x = acc[mb][nb][half*2]   + bias[n];
                o.y = acc[mb][nb][half*2+1] + bias[n+1];
                if (EPI == 1) {
                    const int buf = n >> 10;
                    if (buf == 0) { o.x *= 0.125f; o.y *= 0.125f; }
                    __nv_bfloat16* dh = (buf == 0) ? qh : (buf == 1) ? kh : vh;
                    __nv_bfloat16* dl = (buf == 0) ? ql : (buf == 1) ? kl : vl;
                    const int nn = n & 1023, h = nn >> 6, d = nn & 63;
                    const int b = mrow >> 11, s = mrow & 2047;
                    const size_t off = ((size_t)((b*NH + h)*SEQ + s))*HD + d;
                    const uint32_t hv = pack_bf2(o.x, o.y);
                    __nv_bfloat162 hv2 = *(__nv_bfloat162*)&hv;
                    const uint32_t lv = pack_bf2(o.x - __bfloat162float(hv2.x),
                                                 o.y - __bfloat162float(hv2.y));
                    *(uint32_t*)&dh[off] = hv;
                    *(uint32_t*)&dl[off] = lv;
                } else if (EPI == 2) {
                    const float2 r2 = *(const float2*)&res[(size_t)mrow * N + n];
                    o.x += r2.x; o.y += r2.y;
                    *(float2*)&C[(size_t)mrow * N + n] = o;
                } else {
                    o.x = gelu_exact(o.x); o.y = gelu_exact(o.y);
                    *(float2*)&C[(size_t)mrow * N + n] = o;
                }
            }
        }
    }
}

// ================= flash attention, HMMA bf16 split ========================
// 128 q-rows per block, 8 warps (warp w owns rows w*16..+16), kv tiles of 64.
// smem: Khi @0, Klo @9216, Vhi @18432, Vlo @27648 (rows 64, stride 144B)
#define FLASH_SMEM 36864

__global__ __launch_bounds__(256) void flashb_k(
    const __nv_bfloat16* __restrict__ Qh, const __nv_bfloat16* __restrict__ Ql,
    const __nv_bfloat16* __restrict__ Kh, const __nv_bfloat16* __restrict__ Kl,
    const __nv_bfloat16* __restrict__ Vh, const __nv_bfloat16* __restrict__ Vl,
    float* __restrict__ O)
{
    extern __shared__ char sm[];
    const uint32_t smb = smem_u32(sm);
    const int qb = blockIdx.x, h = blockIdx.y, b = blockIdx.z;
    const int q0 = qb * 128;
    const int tid = threadIdx.x;
    const int wid = tid >> 5, lane = tid & 31;
    const int len = g_len[b];

    if (q0 >= len) return;   // downstream GEMM skips these row tiles entirely

    const size_t base = ((size_t)(b*NH + h)) * SEQ * HD;
    const int qrow = q0 + wid*16 + (lane >> 2);

    uint32_t qhf[4][4], qlf[4][4];
    #pragma unroll
    for (int st = 0; st < 4; ++st)
        #pragma unroll
        for (int rg = 0; rg < 4; ++rg) {
            const int rr = qrow + (rg & 1) * 8;
            const int kk = st*16 + (rg >> 1)*8 + (lane & 3)*2;
            qhf[st][rg] = *(const uint32_t*)&Qh[base + (size_t)rr*HD + kk];
            qlf[st][rg] = *(const uint32_t*)&Ql[base + (size_t)rr*HD + kk];
        }

    float m[2] = {-1e30f, -1e30f}, l[2] = {0.f, 0.f};
    float o[8][4];
    #pragma unroll
    for (int nb = 0; nb < 8; nb++)
        #pragma unroll
        for (int e = 0; e < 4; e++) o[nb][e] = 0.f;

    const int kmax = min(q0 + 127, len - 1);
    for (int k0 = 0; k0 <= kmax; k0 += 64) {
        __syncthreads();
        for (int i = tid; i < 2048; i += 256) {
            const int arr = i >> 9;
            const int idx = i & 511;
            const int r = idx >> 3;
            const int cb = (idx & 7) * 16;
            const __nv_bfloat16* src = (arr == 0) ? Kh : (arr == 1) ? Kl :
                                       (arr == 2) ? Vh : Vl;
            const uint4 val = *(const uint4*)&src[base + (size_t)(k0 + r)*HD + (cb >> 1)];
            *(uint4*)(sm + arr*9216 + r*144 + cb) = val;
        }
        __syncthreads();

        float s[8][4];
        #pragma unroll
        for (int nb = 0; nb < 8; nb++)
            #pragma unroll
            for (int e = 0; e < 4; e++) s[nb][e] = 0.f;
        #pragma unroll
        for (int np = 0; np < 4; ++np) {
            #pragma unroll
            for (int st = 0; st < 4; ++st) {
                const uint32_t a = smb + (uint32_t)((np*16 + (lane & 15))*144 + ((lane >> 4)*16) + st*32);
                uint32_t kh0, kh1, kh2, kh3, kl0, kl1, kl2, kl3;
                ldsm4(a,        kh0, kh1, kh2, kh3);
                ldsm4(a + 9216, kl0, kl1, kl2, kl3);
                mma_bf16(s[np*2],   qhf[st], kh0, kh2);
                mma_bf16(s[np*2],   qhf[st], kl0, kl2);
                mma_bf16(s[np*2],   qlf[st], kh0, kh2);
                mma_bf16(s[np*2+1], qhf[st], kh1, kh3);
                mma_bf16(s[np*2+1], qhf[st], kl1, kl3);
                mma_bf16(s[np*2+1], qlf[st], kh1, kh3);
            }
        }

        if (k0 + 63 >= q0 || k0 + 63 >= len) {
            #pragma unroll
            for (int nb = 0; nb < 8; ++nb)
                #pragma unroll
                for (int e = 0; e < 4; ++e) {
                    const int qq = qrow + (e >> 1) * 8;
                    const int kk = k0 + nb*8 + (lane & 3)*2 + (e & 1);
                    if (kk > qq || kk >= len) s[nb][e] = -1e30f;
                }
        }

        #pragma unroll
        for (int hh = 0; hh < 2; ++hh) {
            float tm = -1e30f;
            #pragma unroll
            for (int nb = 0; nb < 8; ++nb)
                tm = fmaxf(tm, fmaxf(s[nb][hh*2], s[nb][hh*2+1]));
            tm = fmaxf(tm, __shfl_xor_sync(0xffffffffu, tm, 1));
            tm = fmaxf(tm, __shfl_xor_sync(0xffffffffu, tm, 2));
            const float mn = fmaxf(m[hh], tm);
            const float alpha = __expf(m[hh] - mn);
            m[hh] = mn;
            float rs = 0.f;
            #pragma unroll
            for (int nb = 0; nb < 8; ++nb) {
                s[nb][hh*2]   = __expf(s[nb][hh*2]   - mn);
                s[nb][hh*2+1] = __expf(s[nb][hh*2+1] - mn);
                rs += s[nb][hh*2] + s[nb][hh*2+1];
            }
            rs += __shfl_xor_sync(0xffffffffu, rs, 1);
            rs += __shfl_xor_sync(0xffffffffu, rs, 2);
            l[hh] = l[hh]*alpha + rs;
            #pragma unroll
            for (int nb = 0; nb < 8; ++nb) {
                o[nb][hh*2] *= alpha; o[nb][hh*2+1] *= alpha;
            }
        }

        #pragma unroll
        for (int st = 0; st < 4; ++st) {
            uint32_t ph[4], pl[4];
            #pragma unroll
            for (int j = 0; j < 2; ++j) {
                const float e0 = s[2*st+j][0], e1 = s[2*st+j][1];
                const float e2 = s[2*st+j][2], e3 = s[2*st+j][3];
                const uint32_t hv01 = pack_bf2(e0, e1);
                const uint32_t hv23 = pack_bf2(e2, e3);
                const __nv_bfloat162 h01 = *(const __nv_bfloat162*)&hv01;
                const __nv_bfloat162 h23 = *(const __nv_bfloat162*)&hv23;
                ph[(j ? 2 : 0)] = hv01;
                ph[(j ? 3 : 1)] = hv23;
                pl[(j ? 2 : 0)] = pack_bf2(e0 - __bfloat162float(h01.x),
                                           e1 - __bfloat162float(h01.y));
                pl[(j ? 3 : 1)] = pack_bf2(e2 - __bfloat162float(h23.x),
                                           e3 - __bfloat162float(h23.y));
            }
            #pragma unroll
            for (int np = 0; np < 4; ++np) {
                const uint32_t a = smb + 18432u +
                    (uint32_t)((st*16 + (lane & 15))*144 + (np*16 + (lane >> 4)*8)*2);
                uint32_t vh0, vh1, vh2, vh3, vl0, vl1, vl2, vl3;
                ldsm4t(a,        vh0, vh1, vh2, vh3);
                ldsm4t(a + 9216, vl0, vl1, vl2, vl3);
                mma_bf16(o[np*2],   ph, vh0, vh1);
                mma_bf16(o[np*2],   pl, vh0, vh1);
                mma_bf16(o[np*2],   ph, vl0, vl1);
                mma_bf16(o[np*2+1], ph, vh2, vh3);
                mma_bf16(o[np*2+1], pl, vh2, vh3);
                mma_bf16(o[np*2+1], ph, vl2, vl3);
            }
        }
    }

    #pragma unroll
    for (int hh = 0; hh < 2; ++hh) {
        const float inv = 1.f / l[hh];
        const int qq = qrow + hh*8;
        #pragma unroll
        for (int nb = 0; nb < 8; ++nb) {
            float2 ov;
            ov.x = o[nb][hh*2]   * inv;
            ov.y = o[nb][hh*2+1] * inv;
            *(float2*)&O[((size_t)(b*SEQ + qq))*DMODEL + h*HD + nb*8 + (lane & 3)*2] = ov;
        }
    }
}

// ================= LayerNorm ===============================================
// FIN=0: skip padded rows entirely. FIN=1: zero padded rows (final output).
template<int FIN>
__global__ __launch_bounds__(256, 1) void layernorm_k(
    const float* __restrict__ x, const float* __restrict__ g,
    const float* __restrict__ be, float* __restrict__ y)
{
    const int row = blockIdx.x;
    const int tid = threadIdx.x;
    const int b = row >> 11, sidx = row & 2047;
    if (sidx >= g_len[b]) {
        if (FIN == 1)
            *(float4*)(y + (size_t)row*DMODEL + tid*4) = make_float4(0.f, 0.f, 0.f, 0.f);
        return;
    }
    const float4 v = *(const float4*)(x + (size_t)row*DMODEL + tid*4);
    float s  = v.x + v.y + v.z + v.w;
    float s2 = v.x*v.x + v.y*v.y + v.z*v.z + v.w*v.w;

    __shared__ float red[2][8];
    const int lane = tid & 31, warp = tid >> 5;
    #pragma unroll
    for (int off = 16; off > 0; off >>= 1) {
        s  += __shfl_xor_sync(0xffffffffu, s, off);
        s2 += __shfl_xor_sync(0xffffffffu, s2, off);
    }
    if (lane == 0) { red[0][warp] = s; red[1][warp] = s2; }
    __syncthreads();
    float ts = 0.f, ts2 = 0.f;
    #pragma unroll
    for (int w = 0; w < 8; w++) { ts += red[0][w]; ts2 += red[1][w]; }
    const float mu  = ts * (1.f/DMODEL);
    const float var = ts2 * (1.f/DMODEL) - mu*mu;
    const float r   = rsqrtf(var + 1e-5f);

    const float4 gg = *(const float4*)(g  + tid*4);
    const float4 bb = *(const float4*)(be + tid*4);
    float4 o;
    o.x = (v.x - mu)*r*gg.x + bb.x;
    o.y = (v.y - mu)*r*gg.y + bb.y;
    o.z = (v.z - mu)*r*gg.z + bb.z;
    o.w = (v.w - mu)*r*gg.w + bb.w;
    *(float4*)(y + (size_t)row*DMODEL + tid*4) = o;
}

// ================= launch ==================================================
extern "C" void kernel_launch(void* const* d_in, const int* in_sizes, int n_in,
                              void* d_out, int out_size)
{
    (void)in_sizes; (void)n_in; (void)out_size;
    const float* src = (const float*)d_in[0];
    const void* pad = d_in[2];
    const float *Wq = (const float*)d_in[3],  *bq = (const float*)d_in[4];
    const float *Wk = (const float*)d_in[5],  *bk = (const float*)d_in[6];
    const float *Wv = (const float*)d_in[7],  *bv = (const float*)d_in[8];
    const float *Wo = (const float*)d_in[9],  *bo = (const float*)d_in[10];
    const float *W1 = (const float*)d_in[11], *b1 = (const float*)d_in[12];
    const float *W2 = (const float*)d_in[13], *b2 = (const float*)d_in[14];
    const float *g1 = (const float*)d_in[15], *be1 = (const float*)d_in[16];
    const float *g2 = (const float*)d_in[17], *be2 = (const float*)d_in[18];
    float* out = (float*)d_out;

    float *attn, *x1, *src2, *ff, *bqkv;
    __nv_bfloat16 *qh, *ql, *kh, *kl, *vh, *vl;
    __nv_bfloat16 *wqh, *wql, *woh, *wol, *w1h, *w1l, *w2h, *w2l;
    cudaGetSymbolAddress((void**)&attn, g_attn);
    cudaGetSymbolAddress((void**)&x1,   g_x1);
    cudaGetSymbolAddress((void**)&src2, g_src2);
    cudaGetSymbolAddress((void**)&ff,   g_ff);
    cudaGetSymbolAddress((void**)&bqkv, g_bqkv);
    cudaGetSymbolAddress((void**)&qh,   g_qh);
    cudaGetSymbolAddress((void**)&ql,   g_ql);
    cudaGetSymbolAddress((void**)&kh,   g_kh);
    cudaGetSymbolAddress((void**)&kl,   g_kl);
    cudaGetSymbolAddress((void**)&vh,   g_vh);
    cudaGetSymbolAddress((void**)&vl,   g_vl);
    cudaGetSymbolAddress((void**)&wqh,  g_wqkv_hi);
    cudaGetSymbolAddress((void**)&wql,  g_wqkv_lo);
    cudaGetSymbolAddress((void**)&woh,  g_wo_hi);
    cudaGetSymbolAddress((void**)&wol,  g_wo_lo);
    cudaGetSymbolAddress((void**)&w1h,  g_w1_hi);
    cudaGetSymbolAddress((void**)&w1l,  g_w1_lo);
    cudaGetSymbolAddress((void**)&w2h,  g_w2_hi);
    cudaGetSymbolAddress((void**)&w2l,  g_w2_lo);

    len_k<<<BATCH, 256>>>(pad);

    const dim3 tb(32, 8);
    tsplit_k<<<dim3(32, 32), tb>>>(Wq, wqh,             wql,             1024, 1024);
    tsplit_k<<<dim3(32, 32), tb>>>(Wk, wqh + 1024*1024, wql + 1024*1024, 1024, 1024);
    tsplit_k<<<dim3(32, 32), tb>>>(Wv, wqh + 2048*1024, wql + 2048*1024, 1024, 1024);
    tsplit_k<<<dim3(32, 32), tb>>>(Wo, woh, wol, 1024, 1024);
    tsplit_k<<<dim3(128, 32), tb>>>(W1, w1h, w1l, 1024, 4096);
    tsplit_k<<<dim3(32, 128), tb>>>(W2, w2h, w2l, 4096, 1024);
    catb_k<<<12, 256>>>(bq, bk, bv);

    cudaFuncSetAttribute(hgemm_k<1>, cudaFuncAttributeMaxDynamicSharedMemorySize, GEMM_SMEM);
    cudaFuncSetAttribute(hgemm_k<2>, cudaFuncAttributeMaxDynamicSharedMemorySize, GEMM_SMEM);
    cudaFuncSetAttribute(hgemm_k<3>, cudaFuncAttributeMaxDynamicSharedMemorySize, GEMM_SMEM);

    // QKV fused: [4096,1024] @ [1024,3072] -> bf16 hi/lo q,k,v
    hgemm_k<1><<<dim3(24, 32), 256, GEMM_SMEM>>>(src, wqh, wql, bqkv, nullptr,
                                                 nullptr, qh, ql, kh, kl, vh, vl,
                                                 3072, 1024);

    cudaFuncSetAttribute(flashb_k, cudaFuncAttributeMaxDynamicSharedMemorySize, FLASH_SMEM);
    flashb_k<<<dim3(SEQ/128, NH, BATCH), 256, FLASH_SMEM>>>(qh, ql, kh, kl, vh, vl, attn);

    hgemm_k<2><<<dim3(8, 32), 256, GEMM_SMEM>>>(attn, woh, wol, bo, src, x1,
                                                nullptr, nullptr, nullptr, nullptr,
                                                nullptr, nullptr, 1024, 1024);
    layernorm_k<0><<<ROWS, 256>>>(x1, g1, be1, src2);

    hgemm_k<3><<<dim3(32, 32), 256, GEMM_SMEM>>>(src2, w1h, w1l, b1, nullptr, ff,
                                                 nullptr, nullptr, nullptr, nullptr,
                                                 nullptr, nullptr, 4096, 1024);
    hgemm_k<2><<<dim3(8, 32), 256, GEMM_SMEM>>>(ff, w2h, w2l, b2, src2, x1,
                                                nullptr, nullptr, nullptr, nullptr,
                                                nullptr, nullptr, 1024, 4096);
    layernorm_k<1><<<ROWS, 256>>>(x1, g2, be2, out);
}

// round 8
// speedup vs baseline: 1.1332x; 1.0705x over previous
#include <cuda_runtime.h>
#include <cuda_bf16.h>
#include <math.h>
#include <stdint.h>

#define BATCH 2
#define SEQ 2048
#define DMODEL 1024
#define NH 16
#define HD 64
#define DFF 4096
#define ROWS (BATCH*SEQ)   // 4096

// ================= scratch (__device__ globals; no runtime alloc) ==========
__device__ float g_attn[ROWS*DMODEL];
__device__ float g_x1[ROWS*DMODEL];
__device__ float g_src2[ROWS*DMODEL];
__device__ float g_ff[(size_t)ROWS*DFF];
__device__ int   g_len[BATCH];
__device__ float g_bqkv[3072];
// Q/K/V as bf16 hi/lo pairs, layout [B,H,S,hd]; Q pre-scaled by 0.125
__device__ __nv_bfloat16 g_qh[BATCH*NH*SEQ*HD];
__device__ __nv_bfloat16 g_ql[BATCH*NH*SEQ*HD];
__device__ __nv_bfloat16 g_kh[BATCH*NH*SEQ*HD];
__device__ __nv_bfloat16 g_kl[BATCH*NH*SEQ*HD];
__device__ __nv_bfloat16 g_vh[BATCH*NH*SEQ*HD];
__device__ __nv_bfloat16 g_vl[BATCH*NH*SEQ*HD];
// transposed + hi/lo split weights, bf16 [N,K]
__device__ __nv_bfloat16 g_wqkv_hi[3072*1024];
__device__ __nv_bfloat16 g_wqkv_lo[3072*1024];
__device__ __nv_bfloat16 g_wo_hi[1024*1024];
__device__ __nv_bfloat16 g_wo_lo[1024*1024];
__device__ __nv_bfloat16 g_w1_hi[4096*1024];
__device__ __nv_bfloat16 g_w1_lo[4096*1024];
__device__ __nv_bfloat16 g_w2_hi[1024*4096];
__device__ __nv_bfloat16 g_w2_lo[1024*4096];

// ================= helpers =================================================
__device__ __forceinline__ uint32_t smem_u32(const void* p) {
    uint32_t a;
    asm("{ .reg .u64 t; cvta.to.shared.u64 t, %1; cvt.u32.u64 %0, t; }" : "=r"(a) : "l"(p));
    return a;
}
__device__ __forceinline__ void ldsm4(uint32_t a, uint32_t& r0, uint32_t& r1,
                                      uint32_t& r2, uint32_t& r3) {
    asm volatile("ldmatrix.sync.aligned.m8n8.x4.shared.b16 {%0,%1,%2,%3}, [%4];"
        : "=r"(r0), "=r"(r1), "=r"(r2), "=r"(r3) : "r"(a));
}
__device__ __forceinline__ void ldsm4t(uint32_t a, uint32_t& r0, uint32_t& r1,
                                       uint32_t& r2, uint32_t& r3) {
    asm volatile("ldmatrix.sync.aligned.m8n8.x4.trans.shared.b16 {%0,%1,%2,%3}, [%4];"
        : "=r"(r0), "=r"(r1), "=r"(r2), "=r"(r3) : "r"(a));
}
__device__ __forceinline__ void mma_bf16(float* d, const uint32_t* a,
                                         uint32_t b0, uint32_t b1) {
    asm volatile("mma.sync.aligned.m16n8k16.row.col.f32.bf16.bf16.f32 "
        "{%0,%1,%2,%3}, {%4,%5,%6,%7}, {%8,%9}, {%0,%1,%2,%3};"
        : "+f"(d[0]), "+f"(d[1]), "+f"(d[2]), "+f"(d[3])
        : "r"(a[0]), "r"(a[1]), "r"(a[2]), "r"(a[3]), "r"(b0), "r"(b1));
}
__device__ __forceinline__ float gelu_exact(float x) {
    return 0.5f * x * (1.0f + erff(x * 0.70710678118654752f));
}
__device__ __forceinline__ uint32_t pack_bf2(float a, float b) {
    __nv_bfloat162 t = __floats2bfloat162_rn(a, b);
    return *(uint32_t*)&t;
}

// ================= len + bias concat (fused, launch 0) =====================
__global__ void len_k(const void* __restrict__ mask,
                      const float* __restrict__ bq, const float* __restrict__ bk,
                      const float* __restrict__ bv)
{
    if (blockIdx.x >= BATCH) {
        const int i = (blockIdx.x - BATCH) * 256 + threadIdx.x;
        if (i < 3072)
            g_bqkv[i] = (i < 1024) ? bq[i] : (i < 2048) ? bk[i-1024] : bv[i-2048];
        return;
    }
    const int b = blockIdx.x;
    __shared__ int sbyte, smin;
    if (threadIdx.x == 0) { sbyte = 0; smin = SEQ; }
    __syncthreads();
    const unsigned* w = (const unsigned*)mask;
    for (int i = threadIdx.x; i < 1024; i += blockDim.x)
        if (w[i] > 1u) { sbyte = 1; break; }
    __syncthreads();
    int local = SEQ;
    if (sbyte) {
        const unsigned char* m = (const unsigned char*)mask + (size_t)b * SEQ;
        for (int s = threadIdx.x; s < SEQ; s += blockDim.x)
            if (m[s]) { local = s; break; }
    } else {
        const int* m = (const int*)mask + (size_t)b * SEQ;
        for (int s = threadIdx.x; s < SEQ; s += blockDim.x)
            if (m[s]) { local = s; break; }
    }
    atomicMin(&smin, local);
    __syncthreads();
    if (threadIdx.x == 0) g_len[b] = smin;
}

// ================= weight transpose + hi/lo split ==========================
__device__ __forceinline__ void tsplit_body(const float* __restrict__ W,
                                            __nv_bfloat16* __restrict__ hi,
                                            __nv_bfloat16* __restrict__ lo,
                                            int K, int N, int bx, int by)
{
    __shared__ float t[32][33];
    const int n0 = bx * 32, k0 = by * 32;
    const int tx = threadIdx.x, ty = threadIdx.y;
    #pragma unroll
    for (int i = 0; i < 4; i++)
        t[ty + i*8][tx] = W[(size_t)(k0 + ty + i*8) * N + n0 + tx];
    __syncthreads();
    #pragma unroll
    for (int i = 0; i < 4; i++) {
        const float v = t[tx][ty + i*8];
        const __nv_bfloat16 h = __float2bfloat16(v);
        const __nv_bfloat16 l = __float2bfloat16(v - __bfloat162float(h));
        const size_t o = (size_t)(n0 + ty + i*8) * K + k0 + tx;
        hi[o] = h; lo[o] = l;
    }
}

__global__ void tsplit_k(const float* __restrict__ W,
                         __nv_bfloat16* __restrict__ hi,
                         __nv_bfloat16* __restrict__ lo, int K, int N)
{
    tsplit_body(W, hi, lo, K, N, blockIdx.x, blockIdx.y);
}

// Wq/Wk/Wv (each 1024x1024) in one launch, z selects
__global__ void tsplit3_k(const float* __restrict__ Wq,
                          const float* __restrict__ Wk,
                          const float* __restrict__ Wv,
                          __nv_bfloat16* __restrict__ hi,
                          __nv_bfloat16* __restrict__ lo)
{
    const int z = blockIdx.z;
    const float* W = (z == 0) ? Wq : (z == 1) ? Wk : Wv;
    tsplit_body(W, hi + (size_t)z*1024*1024, lo + (size_t)z*1024*1024,
                1024, 1024, blockIdx.x, blockIdx.y);
}

// W1 (1024x4096) and W2 (4096x1024) in one launch
__global__ void tsplitw12_k(const float* __restrict__ W1,
                            const float* __restrict__ W2,
                            __nv_bfloat16* __restrict__ h1, __nv_bfloat16* __restrict__ l1,
                            __nv_bfloat16* __restrict__ h2, __nv_bfloat16* __restrict__ l2)
{
    if (blockIdx.z == 0) {
        if (blockIdx.x >= 128 || blockIdx.y >= 32) return;
        tsplit_body(W1, h1, l1, 1024, 4096, blockIdx.x, blockIdx.y);
    } else {
        if (blockIdx.x >= 32 || blockIdx.y >= 128) return;
        tsplit_body(W2, h2, l2, 4096, 1024, blockIdx.x, blockIdx.y);
    }
}

// ================= HMMA bf16 split GEMM (unchanged from R7 best) ===========
#define ASTR 144
#define SM_AHI 0
#define SM_ALO (128*ASTR)
#define SM_BHI (2*128*ASTR)
#define SM_BLO (3*128*ASTR)
#define GEMM_SMEM (4*128*ASTR)        // 73728

template<int EPI>
__global__ __launch_bounds__(256, 2) void hgemm_k(
    const float* __restrict__ A,
    const __nv_bfloat16* __restrict__ Bhi,
    const __nv_bfloat16* __restrict__ Blo,
    const float* __restrict__ bias,
    const float* __restrict__ res,
    float* __restrict__ C,
    __nv_bfloat16* __restrict__ qh, __nv_bfloat16* __restrict__ ql,
    __nv_bfloat16* __restrict__ kh, __nv_bfloat16* __restrict__ kl,
    __nv_bfloat16* __restrict__ vh, __nv_bfloat16* __restrict__ vl,
    int N, int K)
{
    extern __shared__ char sm[];
    const uint32_t smb = smem_u32(sm);
    const int tid = threadIdx.x;
    const int wid = tid >> 5, lane = tid & 31;
    const int wm = wid & 3, wn = wid >> 2;
    const int row0 = blockIdx.y * 128;
    const int col0 = blockIdx.x * 128;

    if ((row0 & (SEQ-1)) >= g_len[row0 >> 11]) return;

    float acc[2][8][4];
    #pragma unroll
    for (int mb = 0; mb < 2; mb++)
        #pragma unroll
        for (int nb = 0; nb < 8; nb++)
            #pragma unroll
            for (int e = 0; e < 4; e++) acc[mb][nb][e] = 0.f;

    const int nch = K >> 6;
    const int lm_row  = lane & 15;
    const int lm_colb = (lane >> 4) * 16;

    for (int c = 0; c < nch; ++c) {
        __syncthreads();
        const float* Ab = A + (size_t)row0 * K + c * 64;
        #pragma unroll
        for (int i = 0; i < 8; ++i) {
            const int f = i * 256 + tid;
            const int r = f >> 4;
            const int cc = (f & 15) * 4;
            const float4 v = *(const float4*)(Ab + (size_t)r * K + cc);
            const __nv_bfloat16 h0 = __float2bfloat16(v.x), h1 = __float2bfloat16(v.y);
            const __nv_bfloat16 h2 = __float2bfloat16(v.z), h3 = __float2bfloat16(v.w);
            const uint32_t off = (uint32_t)(r * ASTR + cc * 2);
            *(uint32_t*)(sm + SM_AHI + off)     = pack_bf2(__bfloat162float(h0), __bfloat162float(h1));
            *(uint32_t*)(sm + SM_AHI + off + 4) = pack_bf2(__bfloat162float(h2), __bfloat162float(h3));
            *(uint32_t*)(sm + SM_ALO + off)     = pack_bf2(v.x - __bfloat162float(h0), v.y - __bfloat162float(h1));
            *(uint32_t*)(sm + SM_ALO + off + 4) = pack_bf2(v.z - __bfloat162float(h2), v.w - __bfloat162float(h3));
        }
        #pragma unroll
        for (int i = 0; i < 8; ++i) {
            const int f = i * 256 + tid;
            const int arr = f >> 10;
            const int idx = f & 1023;
            const int r = idx >> 3;
            const int cb = (idx & 7) * 16;
            const __nv_bfloat16* srcb = arr ? Blo : Bhi;
            const uint4 v = *(const uint4*)(srcb + (size_t)(col0 + r) * K + c * 64 + (cb >> 1));
            *(uint4*)(sm + (arr ? SM_BLO : SM_BHI) + r * ASTR + cb) = v;
        }
        __syncthreads();

        #pragma unroll
        for (int st = 0; st < 4; ++st) {
            const int kb = st * 32;
            uint32_t ah[2][4], al[2][4];
            #pragma unroll
            for (int mb = 0; mb < 2; ++mb) {
                const uint32_t arow = (uint32_t)((wm*32 + mb*16 + lm_row) * ASTR + lm_colb + kb);
                ldsm4(smb + SM_AHI + arow, ah[mb][0], ah[mb][1], ah[mb][2], ah[mb][3]);
                ldsm4(smb + SM_ALO + arow, al[mb][0], al[mb][1], al[mb][2], al[mb][3]);
            }
            #pragma unroll
            for (int np = 0; np < 4; ++np) {
                const uint32_t brow = (uint32_t)((wn*64 + np*16 + lm_row) * ASTR + lm_colb + kb);
                uint32_t bh0, bh1, bh2, bh3, bl0, bl1, bl2, bl3;
                ldsm4(smb + SM_BHI + brow, bh0, bh1, bh2, bh3);
                ldsm4(smb + SM_BLO + brow, bl0, bl1, bl2, bl3);
                #pragma unroll
                for (int mb = 0; mb < 2; ++mb) {
                    mma_bf16(acc[mb][np*2],   ah[mb], bh0, bh2);
                    mma_bf16(acc[mb][np*2],   ah[mb], bl0, bl2);
                    mma_bf16(acc[mb][np*2],   al[mb], bh0, bh2);
                    mma_bf16(acc[mb][np*2+1], ah[mb], bh1, bh3);
                    mma_bf16(acc[mb][np*2+1], ah[mb], bl1, bl3);
                    mma_bf16(acc[mb][np*2+1], al[mb], bh1, bh3);
                }
            }
        }
    }

    const int g = lane >> 2;
    const int cpair = (lane & 3) * 2;
    #pragma unroll
    for (int mb = 0; mb < 2; ++mb) {
        #pragma unroll
        for (int half = 0; half < 2; ++half) {
            const int mrow = row0 + wm*32 + mb*16 + g + half*8;
            #pragma unroll
            for (int nb = 0; nb < 8; ++nb) {
                const int n = col0 + wn*64 + nb*8 + cpair;
                float2 o;
                o.x = acc[mb][nb][half*2]   + bias[n];
                o.y = acc[mb][nb][half*2+1] + bias[n+1];
                if (EPI == 1) {
                    const int buf = n >> 10;
                    if (buf == 0) { o.x *= 0.125f; o.y *= 0.125f; }
                    __nv_bfloat16* dh = (buf == 0) ? qh : (buf == 1) ? kh : vh;
                    __nv_bfloat16* dl = (buf == 0) ? ql : (buf == 1) ? kl : vl;
                    const int nn = n & 1023, h = nn >> 6, d = nn & 63;
                    const int b = mrow >> 11, s = mrow & 2047;
                    const size_t off = ((size_t)((b*NH + h)*SEQ + s))*HD + d;
                    const uint32_t hv = pack_bf2(o.x, o.y);
                    __nv_bfloat162 hv2 = *(__nv_bfloat162*)&hv;
                    const uint32_t lv = pack_bf2(o.x - __bfloat162float(hv2.x),
                                                 o.y - __bfloat162float(hv2.y));
                    *(uint32_t*)&dh[off] = hv;
                    *(uint32_t*)&dl[off] = lv;
                } else if (EPI == 2) {
                    const float2 r2 = *(const float2*)&res[(size_t)mrow * N + n];
                    o.x += r2.x; o.y += r2.y;
                    *(float2*)&C[(size_t)mrow * N + n] = o;
                } else {
                    o.x = gelu_exact(o.x); o.y = gelu_exact(o.y);
                    *(float2*)&C[(size_t)mrow * N + n] = o;
                }
            }
        }
    }
}

// ================= flash attention, HMMA bf16 split, cp.async 2-stage ======
// 128 q-rows per block, 8 warps, kv tiles of 64, K/V double-buffered.
// stage layout: Khi @0, Klo @9216, Vhi @18432, Vlo @27648 (stride 144B)
#define FSTG 36864
#define FLASH_SMEM (2*FSTG)   // 73728

__global__ __launch_bounds__(256) void flashb_k(
    const __nv_bfloat16* __restrict__ Qh, const __nv_bfloat16* __restrict__ Ql,
    const __nv_bfloat16* __restrict__ Kh, const __nv_bfloat16* __restrict__ Kl,
    const __nv_bfloat16* __restrict__ Vh, const __nv_bfloat16* __restrict__ Vl,
    float* __restrict__ O)
{
    extern __shared__ char sm[];
    const uint32_t smb = smem_u32(sm);
    const int qb = blockIdx.x, h = blockIdx.y, b = blockIdx.z;
    const int q0 = qb * 128;
    const int tid = threadIdx.x;
    const int wid = tid >> 5, lane = tid & 31;
    const int len = g_len[b];

    if (q0 >= len) return;

    const size_t base = ((size_t)(b*NH + h)) * SEQ * HD;
    const int qrow = q0 + wid*16 + (lane >> 2);

    // cp.async one 64-row K/V hi/lo tile into stage buf
    auto prefetch = [&](int k0, int buf) {
        const uint32_t sb = smb + (uint32_t)buf * FSTG;
        #pragma unroll
        for (int i = 0; i < 8; ++i) {
            const int f = i * 256 + tid;      // 0..2047
            const int arr = f >> 9;           // 0:Kh 1:Kl 2:Vh 3:Vl
            const int idx = f & 511;
            const int r = idx >> 3;
            const int cb = (idx & 7) * 16;    // byte col (16B seg)
            const __nv_bfloat16* src = (arr == 0) ? Kh : (arr == 1) ? Kl :
                                       (arr == 2) ? Vh : Vl;
            const __nv_bfloat16* gp = src + base + (size_t)(k0 + r)*HD + (cb >> 1);
            asm volatile("cp.async.cg.shared.global [%0], [%1], 16;"
                         :: "r"(sb + (uint32_t)(arr*9216 + r*144 + cb)), "l"(gp));
        }
        asm volatile("cp.async.commit_group;" ::: "memory");
    };

    uint32_t qhf[4][4], qlf[4][4];
    #pragma unroll
    for (int st = 0; st < 4; ++st)
        #pragma unroll
        for (int rg = 0; rg < 4; ++rg) {
            const int rr = qrow + (rg & 1) * 8;
            const int kk = st*16 + (rg >> 1)*8 + (lane & 3)*2;
            qhf[st][rg] = *(const uint32_t*)&Qh[base + (size_t)rr*HD + kk];
            qlf[st][rg] = *(const uint32_t*)&Ql[base + (size_t)rr*HD + kk];
        }

    float m[2] = {-1e30f, -1e30f}, l[2] = {0.f, 0.f};
    float o[8][4];
    #pragma unroll
    for (int nb = 0; nb < 8; nb++)
        #pragma unroll
        for (int e = 0; e < 4; e++) o[nb][e] = 0.f;

    const int kmax = min(q0 + 127, len - 1);
    const int nt = (kmax >> 6) + 1;

    prefetch(0, 0);
    for (int t = 0; t < nt; ++t) {
        const int k0 = t << 6;
        if (t + 1 < nt) {
            prefetch(k0 + 64, (t + 1) & 1);
            asm volatile("cp.async.wait_group 1;" ::: "memory");
        } else {
            asm volatile("cp.async.wait_group 0;" ::: "memory");
        }
        __syncthreads();
        const uint32_t sbuf = smb + (uint32_t)(t & 1) * FSTG;

        float s[8][4];
        #pragma unroll
        for (int nb = 0; nb < 8; nb++)
            #pragma unroll
            for (int e = 0; e < 4; e++) s[nb][e] = 0.f;
        #pragma unroll
        for (int np = 0; np < 4; ++np) {
            #pragma unroll
            for (int st = 0; st < 4; ++st) {
                const uint32_t a = sbuf + (uint32_t)((np*16 + (lane & 15))*144 + ((lane >> 4)*16) + st*32);
                uint32_t kh0, kh1, kh2, kh3, kl0, kl1, kl2, kl3;
                ldsm4(a,        kh0, kh1, kh2, kh3);
                ldsm4(a + 9216, kl0, kl1, kl2, kl3);
                mma_bf16(s[np*2],   qhf[st], kh0, kh2);
                mma_bf16(s[np*2],   qhf[st], kl0, kl2);
                mma_bf16(s[np*2],   qlf[st], kh0, kh2);
                mma_bf16(s[np*2+1], qhf[st], kh1, kh3);
                mma_bf16(s[np*2+1], qhf[st], kl1, kl3);
                mma_bf16(s[np*2+1], qlf[st], kh1, kh3);
            }
        }

        if (k0 + 63 >= q0 || k0 + 63 >= len) {
            #pragma unroll
            for (int nb = 0; nb < 8; ++nb)
                #pragma unroll
                for (int e = 0; e < 4; ++e) {
                    const int qq = qrow + (e >> 1) * 8;
                    const int kk = k0 + nb*8 + (lane & 3)*2 + (e & 1);
                    if (kk > qq || kk >= len) s[nb][e] = -1e30f;
                }
        }

        #pragma unroll
        for (int hh = 0; hh < 2; ++hh) {
            float tm = -1e30f;
            #pragma unroll
            for (int nb = 0; nb < 8; ++nb)
                tm = fmaxf(tm, fmaxf(s[nb][hh*2], s[nb][hh*2+1]));
            tm = fmaxf(tm, __shfl_xor_sync(0xffffffffu, tm, 1));
            tm = fmaxf(tm, __shfl_xor_sync(0xffffffffu, tm, 2));
            const float mn = fmaxf(m[hh], tm);
            const float alpha = __expf(m[hh] - mn);
            m[hh] = mn;
            float rs = 0.f;
            #pragma unroll
            for (int nb = 0; nb < 8; ++nb) {
                s[nb][hh*2]   = __expf(s[nb][hh*2]   - mn);
                s[nb][hh*2+1] = __expf(s[nb][hh*2+1] - mn);
                rs += s[nb][hh*2] + s[nb][hh*2+1];
            }
            rs += __shfl_xor_sync(0xffffffffu, rs, 1);
            rs += __shfl_xor_sync(0xffffffffu, rs, 2);
            l[hh] = l[hh]*alpha + rs;
            #pragma unroll
            for (int nb = 0; nb < 8; ++nb) {
                o[nb][hh*2] *= alpha; o[nb][hh*2+1] *= alpha;
            }
        }

        #pragma unroll
        for (int st = 0; st < 4; ++st) {
            uint32_t ph[4], pl[4];
            #pragma unroll
            for (int j = 0; j < 2; ++j) {
                const float e0 = s[2*st+j][0], e1 = s[2*st+j][1];
                const float e2 = s[2*st+j][2], e3 = s[2*st+j][3];
                const uint32_t hv01 = pack_bf2(e0, e1);
                const uint32_t hv23 = pack_bf2(e2, e3);
                const __nv_bfloat162 h01 = *(const __nv_bfloat162*)&hv01;
                const __nv_bfloat162 h23 = *(const __nv_bfloat162*)&hv23;
                ph[(j ? 2 : 0)] = hv01;
                ph[(j ? 3 : 1)] = hv23;
                pl[(j ? 2 : 0)] = pack_bf2(e0 - __bfloat162float(h01.x),
                                           e1 - __bfloat162float(h01.y));
                pl[(j ? 3 : 1)] = pack_bf2(e2 - __bfloat162float(h23.x),
                                           e3 - __bfloat162float(h23.y));
            }
            #pragma unroll
            for (int np = 0; np < 4; ++np) {
                const uint32_t a = sbuf + 18432u +
                    (uint32_t)((st*16 + (lane & 15))*144 + (np*16 + (lane >> 4)*8)*2);
                uint32_t vh0, vh1, vh2, vh3, vl0, vl1, vl2, vl3;
                ldsm4t(a,        vh0, vh1, vh2, vh3);
                ldsm4t(a + 9216, vl0, vl1, vl2, vl3);
                mma_bf16(o[np*2],   ph, vh0, vh1);
                mma_bf16(o[np*2],   pl, vh0, vh1);
                mma_bf16(o[np*2],   ph, vl0, vl1);
                mma_bf16(o[np*2+1], ph, vh2, vh3);
                mma_bf16(o[np*2+1], pl, vh2, vh3);
                mma_bf16(o[np*2+1], ph, vl2, vl3);
            }
        }
        __syncthreads();   // all reads of sbuf done before t+2's prefetch overwrites
    }

    #pragma unroll
    for (int hh = 0; hh < 2; ++hh) {
        const float inv = 1.f / l[hh];
        const int qq = qrow + hh*8;
        #pragma unroll
        for (int nb = 0; nb < 8; ++nb) {
            float2 ov;
            ov.x = o[nb][hh*2]   * inv;
            ov.y = o[nb][hh*2+1] * inv;
            *(float2*)&O[((size_t)(b*SEQ + qq))*DMODEL + h*HD + nb*8 + (lane & 3)*2] = ov;
        }
    }
}

// ================= LayerNorm ===============================================
template<int FIN>
__global__ __launch_bounds__(256, 1) void layernorm_k(
    const float* __restrict__ x, const float* __restrict__ g,
    const float* __restrict__ be, float* __restrict__ y)
{
    const int row = blockIdx.x;
    const int tid = threadIdx.x;
    const int b = row >> 11, sidx = row & 2047;
    if (sidx >= g_len[b]) {
        if (FIN == 1)
            *(float4*)(y + (size_t)row*DMODEL + tid*4) = make_float4(0.f, 0.f, 0.f, 0.f);
        return;
    }
    const float4 v = *(const float4*)(x + (size_t)row*DMODEL + tid*4);
    float s  = v.x + v.y + v.z + v.w;
    float s2 = v.x*v.x + v.y*v.y + v.z*v.z + v.w*v.w;

    __shared__ float red[2][8];
    const int lane = tid & 31, warp = tid >> 5;
    #pragma unroll
    for (int off = 16; off > 0; off >>= 1) {
        s  += __shfl_xor_sync(0xffffffffu, s, off);
        s2 += __shfl_xor_sync(0xffffffffu, s2, off);
    }
    if (lane == 0) { red[0][warp] = s; red[1][warp] = s2; }
    __syncthreads();
    float ts = 0.f, ts2 = 0.f;
    #pragma unroll
    for (int w = 0; w < 8; w++) { ts += red[0][w]; ts2 += red[1][w]; }
    const float mu  = ts * (1.f/DMODEL);
    const float var = ts2 * (1.f/DMODEL) - mu*mu;
    const float r   = rsqrtf(var + 1e-5f);

    const float4 gg = *(const float4*)(g  + tid*4);
    const float4 bb = *(const float4*)(be + tid*4);
    float4 o;
    o.x = (v.x - mu)*r*gg.x + bb.x;
    o.y = (v.y - mu)*r*gg.y + bb.y;
    o.z = (v.z - mu)*r*gg.z + bb.z;
    o.w = (v.w - mu)*r*gg.w + bb.w;
    *(float4*)(y + (size_t)row*DMODEL + tid*4) = o;
}

// ================= launch ==================================================
extern "C" void kernel_launch(void* const* d_in, const int* in_sizes, int n_in,
                              void* d_out, int out_size)
{
    (void)in_sizes; (void)n_in; (void)out_size;
    const float* src = (const float*)d_in[0];
    const void* pad = d_in[2];
    const float *Wq = (const float*)d_in[3],  *bq = (const float*)d_in[4];
    const float *Wk = (const float*)d_in[5],  *bk = (const float*)d_in[6];
    const float *Wv = (const float*)d_in[7],  *bv = (const float*)d_in[8];
    const float *Wo = (const float*)d_in[9],  *bo = (const float*)d_in[10];
    const float *W1 = (const float*)d_in[11], *b1 = (const float*)d_in[12];
    const float *W2 = (const float*)d_in[13], *b2 = (const float*)d_in[14];
    const float *g1 = (const float*)d_in[15], *be1 = (const float*)d_in[16];
    const float *g2 = (const float*)d_in[17], *be2 = (const float*)d_in[18];
    float* out = (float*)d_out;

    float *attn, *x1, *src2, *ff, *bqkv;
    __nv_bfloat16 *qh, *ql, *kh, *kl, *vh, *vl;
    __nv_bfloat16 *wqh, *wql, *woh, *wol, *w1h, *w1l, *w2h, *w2l;
    cudaGetSymbolAddress((void**)&attn, g_attn);
    cudaGetSymbolAddress((void**)&x1,   g_x1);
    cudaGetSymbolAddress((void**)&src2, g_src2);
    cudaGetSymbolAddress((void**)&ff,   g_ff);
    cudaGetSymbolAddress((void**)&bqkv, g_bqkv);
    cudaGetSymbolAddress((void**)&qh,   g_qh);
    cudaGetSymbolAddress((void**)&ql,   g_ql);
    cudaGetSymbolAddress((void**)&kh,   g_kh);
    cudaGetSymbolAddress((void**)&kl,   g_kl);
    cudaGetSymbolAddress((void**)&vh,   g_vh);
    cudaGetSymbolAddress((void**)&vl,   g_vl);
    cudaGetSymbolAddress((void**)&wqh,  g_wqkv_hi);
    cudaGetSymbolAddress((void**)&wql,  g_wqkv_lo);
    cudaGetSymbolAddress((void**)&woh,  g_wo_hi);
    cudaGetSymbolAddress((void**)&wol,  g_wo_lo);
    cudaGetSymbolAddress((void**)&w1h,  g_w1_hi);
    cudaGetSymbolAddress((void**)&w1l,  g_w1_lo);
    cudaGetSymbolAddress((void**)&w2h,  g_w2_hi);
    cudaGetSymbolAddress((void**)&w2l,  g_w2_lo);

    cudaFuncSetAttribute(hgemm_k<1>, cudaFuncAttributeMaxDynamicSharedMemorySize, GEMM_SMEM);
    cudaFuncSetAttribute(hgemm_k<2>, cudaFuncAttributeMaxDynamicSharedMemorySize, GEMM_SMEM);
    cudaFuncSetAttribute(hgemm_k<3>, cudaFuncAttributeMaxDynamicSharedMemorySize, GEMM_SMEM);
    cudaFuncSetAttribute(flashb_k, cudaFuncAttributeMaxDynamicSharedMemorySize, FLASH_SMEM);

    const dim3 tb(32, 8);
    // launch indices arranged so ncu (-s 5 -c 1) captures flashb_k (index 5)
    len_k<<<14, 256>>>(pad, bq, bk, bv);                                  // 0
    tsplit3_k<<<dim3(32, 32, 3), tb>>>(Wq, Wk, Wv, wqh, wql);             // 1
    tsplit_k<<<dim3(32, 32), tb>>>(Wo, woh, wol, 1024, 1024);             // 2
    tsplitw12_k<<<dim3(128, 128, 2), tb>>>(W1, W2, w1h, w1l, w2h, w2l);   // 3
    hgemm_k<1><<<dim3(24, 32), 256, GEMM_SMEM>>>(src, wqh, wql, bqkv, nullptr,
                                                 nullptr, qh, ql, kh, kl, vh, vl,
                                                 3072, 1024);             // 4
    flashb_k<<<dim3(SEQ/128, NH, BATCH), 256, FLASH_SMEM>>>(qh, ql, kh, kl, vh, vl,
                                                            attn);       // 5
    hgemm_k<2><<<dim3(8, 32), 256, GEMM_SMEM>>>(attn, woh, wol, bo, src, x1,
                                                nullptr, nullptr, nullptr, nullptr,
                                                nullptr, nullptr, 1024, 1024);
    layernorm_k<0><<<ROWS, 256>>>(x1, g1, be1, src2);
    hgemm_k<3><<<dim3(32, 32), 256, GEMM_SMEM>>>(src2, w1h, w1l, b1, nullptr, ff,
                                                 nullptr, nullptr, nullptr, nullptr,
                                                 nullptr, nullptr, 4096, 1024);
    hgemm_k<2><<<dim3(8, 32), 256, GEMM_SMEM>>>(ff, w2h, w2l, b2, src2, x1,
                                                nullptr, nullptr, nullptr, nullptr,
                                                nullptr, nullptr, 1024, 4096);
    layernorm_k<1><<<ROWS, 256>>>(x1, g2, be2, out);
}